// round 4
// baseline (speedup 1.0000x reference)
#include <cuda_runtime.h>

#define BNUM  32
#define TENC  4096
#define TPRED 1024
#define DHALF 512
#define DFULL 1024
#define NCLS  4
#define ENC_TS  32     // 4096 / 128
#define PRED_TS 8      // 1024 / 128
#define TCHUNK  128
#define LN_EPS 1e-5f

__device__ float g_part_e[ENC_TS  * BNUM * NCLS * DHALF];  // 8 MB
__device__ float g_part_p[PRED_TS * BNUM * NCLS * DHALF];  // 2 MB
__device__ float g_mean[BNUM * NCLS * DFULL];              // 512 KB
__device__ float g_loss_b[BNUM];
__device__ unsigned int g_ticket_b[BNUM];
__device__ unsigned int g_ticket;

// ---------------------------------------------------------------------------
// Merged masked partial sums (enc + pred, uniform CTA work).
// grid (ENC_TS + PRED_TS, BNUM), 128 threads.
// ---------------------------------------------------------------------------
__global__ void __launch_bounds__(128)
masked_sum_kernel(const float4* __restrict__ enc,
                  const float4* __restrict__ pred,
                  const int*    __restrict__ lab_e,
                  const int*    __restrict__ lab_p) {
    int ts  = blockIdx.x;
    int b   = blockIdx.y;
    int tid = threadIdx.x;

    const float4* x;
    const int*    lab;
    float4*       pp;
    int T, tsl;
    if (ts < ENC_TS) {
        x = enc;  lab = lab_e; pp = (float4*)g_part_e; T = TENC;  tsl = ts;
    } else {
        x = pred; lab = lab_p; pp = (float4*)g_part_p; T = TPRED; tsl = ts - ENC_TS;
    }
    int t0 = tsl * TCHUNK;

    __shared__ int slab[TCHUNK];
    slab[tid] = lab[(size_t)b * T + t0 + tid];
    __syncthreads();

    const float4* xp = x + ((size_t)b * T + t0) * (DHALF / 4) + tid;

    float4 a0 = {0.f,0.f,0.f,0.f};
    float4 a1 = {0.f,0.f,0.f,0.f};
    float4 a2 = {0.f,0.f,0.f,0.f};
    float4 a3 = {0.f,0.f,0.f,0.f};

    #pragma unroll 8
    for (int t = 0; t < TCHUNK; ++t) {
        float4 v = __ldcs(&xp[(size_t)t * (DHALF / 4)]);
        int c = slab[t];
        a0.x += (c == 0) ? v.x : 0.f;  a0.y += (c == 0) ? v.y : 0.f;
        a0.z += (c == 0) ? v.z : 0.f;  a0.w += (c == 0) ? v.w : 0.f;
        a1.x += (c == 1) ? v.x : 0.f;  a1.y += (c == 1) ? v.y : 0.f;
        a1.z += (c == 1) ? v.z : 0.f;  a1.w += (c == 1) ? v.w : 0.f;
        a2.x += (c == 2) ? v.x : 0.f;  a2.y += (c == 2) ? v.y : 0.f;
        a2.z += (c == 2) ? v.z : 0.f;  a2.w += (c == 2) ? v.w : 0.f;
        a3.x += (c == 3) ? v.x : 0.f;  a3.y += (c == 3) ? v.y : 0.f;
        a3.z += (c == 3) ? v.z : 0.f;  a3.w += (c == 3) ? v.w : 0.f;
    }

    size_t base = (((size_t)tsl * BNUM + b) * NCLS) * (DHALF / 4) + tid;
    pp[base + 0 * (DHALF / 4)] = a0;
    pp[base + 1 * (DHALF / 4)] = a1;
    pp[base + 2 * (DHALF / 4)] = a2;
    pp[base + 3 * (DHALF / 4)] = a3;
}

// ---------------------------------------------------------------------------
// Wide tail: grid (8, BNUM), 256 threads. CTA (combo, b) with combo = (c, h)
// reduces partials for its (class, half) into g_mean and counts class c in
// tensor h. Last of the 8 CTAs per b (ticket) runs LN + logits + loss; last
// of those 32 writes the scalar.
// ---------------------------------------------------------------------------
__global__ void __launch_bounds__(256)
tail_kernel(const int*   __restrict__ lab_e,
            const int*   __restrict__ lab_p,
            const int*   __restrict__ label,
            const float* __restrict__ norm_w,
            const float* __restrict__ norm_b,
            const float* __restrict__ head_w,
            const float* __restrict__ head_b,
            float*       __restrict__ out) {
    int combo = blockIdx.x;              // 0..7
    int b     = blockIdx.y;
    int c     = combo >> 1;
    int h     = combo & 1;               // 0 = enc, 1 = pred
    int tid   = threadIdx.x;
    int lane  = tid & 31;
    int wid   = tid >> 5;                // 0..7

    // ---- count class c in tensor h ----
    const int* lab = h ? lab_p : lab_e;
    int T = h ? TPRED : TENC;
    int cnt = 0;
    for (int i = tid; i < T; i += 256)
        cnt += (lab[(size_t)b * T + i] == c);
    #pragma unroll
    for (int o = 16; o; o >>= 1)
        cnt += __shfl_xor_sync(0xffffffffu, cnt, o);
    __shared__ int scnt[8];
    if (lane == 0) scnt[wid] = cnt;
    __syncthreads();

    // ---- reduce partials over t-splits ----
    int d4 = tid & 127;
    int sh = tid >> 7;                   // 0/1: split halves
    const float4* part = h ? (const float4*)g_part_p : (const float4*)g_part_e;
    int S = h ? PRED_TS : ENC_TS;
    size_t stride = (size_t)BNUM * NCLS * (DHALF / 4);
    size_t base   = ((size_t)b * NCLS + c) * (DHALF / 4) + d4;
    float4 acc = {0.f,0.f,0.f,0.f};
    #pragma unroll 8
    for (int s = sh; s < S; s += 2) {
        float4 v = part[(size_t)s * stride + base];
        acc.x += v.x; acc.y += v.y; acc.z += v.z; acc.w += v.w;
    }
    __shared__ float4 s_half[128];
    if (sh == 1) s_half[d4] = acc;
    __syncthreads();
    if (sh == 0) {
        float4 v = s_half[d4];
        acc.x += v.x; acc.y += v.y; acc.z += v.z; acc.w += v.w;
        int tot = 0;
        #pragma unroll
        for (int w = 0; w < 8; ++w) tot += scnt[w];
        float inv = 1.f / fmaxf((float)tot, 1.f);
        acc.x *= inv; acc.y *= inv; acc.z *= inv; acc.w *= inv;
        ((float4*)(g_mean + ((size_t)b * NCLS + c) * DFULL + h * DHALF))[d4] = acc;
    }
    __threadfence();
    __syncthreads();

    // ---- per-b ticket: last of 8 finalizes this b ----
    __shared__ int s_win;
    if (tid == 0) {
        unsigned int t = atomicAdd(&g_ticket_b[b], 1u);
        s_win = (t == 7);
        if (t == 7) g_ticket_b[b] = 0;   // reset for next replay
    }
    __syncthreads();
    if (!s_win) return;
    __threadfence();                     // acquire side

    // ---- LN + logits + loss (256 threads, 8 warps) ----
    __shared__ float s_red[2 * NCLS][8];
    __shared__ float s_mu[NCLS], s_rstd[NCLS];
    __shared__ float s_lg[8][NCLS][NCLS];
    __shared__ float s_logits[NCLS][NCLS];

    int gd = tid * 4;
    float4 f[NCLS];
    #pragma unroll
    for (int cc = 0; cc < NCLS; ++cc) {
        f[cc] = *(const float4*)(g_mean + ((size_t)b * NCLS + cc) * DFULL + gd);
        float s = f[cc].x + f[cc].y + f[cc].z + f[cc].w;
        float q = f[cc].x*f[cc].x + f[cc].y*f[cc].y + f[cc].z*f[cc].z + f[cc].w*f[cc].w;
        #pragma unroll
        for (int o = 16; o; o >>= 1) {
            s += __shfl_xor_sync(0xffffffffu, s, o);
            q += __shfl_xor_sync(0xffffffffu, q, o);
        }
        if (lane == 0) { s_red[cc * 2][wid] = s; s_red[cc * 2 + 1][wid] = q; }
    }
    __syncthreads();
    if (tid < NCLS) {
        float s = 0.f, q = 0.f;
        #pragma unroll
        for (int w = 0; w < 8; ++w) { s += s_red[tid * 2][w]; q += s_red[tid * 2 + 1][w]; }
        float mu  = s / (float)DFULL;
        float var = q / (float)DFULL - mu * mu;
        s_mu[tid]   = mu;
        s_rstd[tid] = rsqrtf(var + LN_EPS);
    }
    __syncthreads();

    {
        float4 w4 = *(const float4*)(norm_w + gd);
        float4 b4 = *(const float4*)(norm_b + gd);
        float4 hw[NCLS];
        #pragma unroll
        for (int n = 0; n < NCLS; ++n)
            hw[n] = *(const float4*)(head_w + (size_t)n * DFULL + gd);

        #pragma unroll
        for (int cc = 0; cc < NCLS; ++cc) {
            float mu = s_mu[cc], r = s_rstd[cc];
            float fx = (f[cc].x - mu) * r * w4.x + b4.x;
            float fy = (f[cc].y - mu) * r * w4.y + b4.y;
            float fz = (f[cc].z - mu) * r * w4.z + b4.z;
            float fw = (f[cc].w - mu) * r * w4.w + b4.w;
            #pragma unroll
            for (int n = 0; n < NCLS; ++n) {
                float v = fx * hw[n].x + fy * hw[n].y + fz * hw[n].z + fw * hw[n].w;
                #pragma unroll
                for (int o = 16; o; o >>= 1)
                    v += __shfl_xor_sync(0xffffffffu, v, o);
                if (lane == 0) s_lg[wid][cc][n] = v;
            }
        }
    }
    __syncthreads();
    if (tid < NCLS * NCLS) {
        int cc = tid >> 2, n = tid & 3;
        float v = 0.f;
        #pragma unroll
        for (int w = 0; w < 8; ++w) v += s_lg[w][cc][n];
        s_logits[cc][n] = v + head_b[n];
    }
    __syncthreads();

    if (tid == 0) {
        float sel_sum = 0.f;
        #pragma unroll
        for (int l = 0; l < NCLS; ++l) {
            int lb = label[b * NCLS + l];
            float m = s_logits[lb][0];
            #pragma unroll
            for (int n = 1; n < NCLS; ++n) m = fmaxf(m, s_logits[lb][n]);
            float se = 0.f;
            #pragma unroll
            for (int n = 0; n < NCLS; ++n) se += expf(s_logits[lb][n] - m);
            sel_sum += s_logits[lb][lb] - m - logf(se);
        }
        g_loss_b[b] = sel_sum;
        __threadfence();
        unsigned int t = atomicAdd(&g_ticket, 1u);
        if (t == BNUM - 1) {
            float tot = 0.f;
            #pragma unroll
            for (int i = 0; i < BNUM; ++i) tot += g_loss_b[i];
            out[0] = -tot / (float)(BNUM * NCLS);
            g_ticket = 0;   // reset for next replay
        }
    }
}

// ---------------------------------------------------------------------------
extern "C" void kernel_launch(void* const* d_in, const int* in_sizes, int n_in,
                              void* d_out, int out_size) {
    const float* enc_out = (const float*)d_in[0];
    const float* pred_out = (const float*)d_in[1];
    const int*   frame_label  = (const int*)d_in[2];
    const int*   frame_tlabel = (const int*)d_in[3];
    const int*   label  = (const int*)d_in[4];
    const float* norm_w = (const float*)d_in[5];
    const float* norm_b = (const float*)d_in[6];
    const float* head_w = (const float*)d_in[7];
    const float* head_b = (const float*)d_in[8];
    float* out = (float*)d_out;

    masked_sum_kernel<<<dim3(ENC_TS + PRED_TS, BNUM), 128>>>(
        (const float4*)enc_out, (const float4*)pred_out,
        frame_label, frame_tlabel);

    tail_kernel<<<dim3(8, BNUM), 256>>>(frame_label, frame_tlabel, label,
                                        norm_w, norm_b, head_w, head_b, out);
}